// round 7
// baseline (speedup 1.0000x reference)
#include <cuda_runtime.h>
#include <cstdint>

// FocusModules, persistent TMA pipeline with a 3-stage ring buffer.
// x: [N, 256] f32.  out (float32): [ mask1 (N) | compressed (N*256) ].
//
// Grid = 148*2 persistent CTAs (512 thr, 16 warps), 2 CTAs/SM.
// Per window: tile rows 0..32 = tokens t0-1..t0+31.
// mean_sim[i] = inv_i * dot(raw_i, s)/32, s[c] = sum_r raw[r][c]*inv_r.
// Loads are issued 2 iterations ahead -> ~2 loads + 1-2 stores in flight
// per CTA at steady state (fixes the DRAM duty-cycle shortfall seen at 69%).

#define WTOK 32
#define NCTA (148 * 2)
#define NBUF 3

struct __align__(128) Smem {
    float tile[NBUF][33 * 256];  // 3 x 33 KB
    float s_s[256];              // weighted column sums
    float inv_s[33];             // per-row 1/||x||
    float ms_s[WTOK];            // per-token mean similarity
    unsigned long long mbar[NBUF];
};

__device__ __forceinline__ uint32_t smem_u32(const void* p) {
    return (uint32_t)__cvta_generic_to_shared(p);
}
__device__ __forceinline__ float warp_sum(float v) {
    #pragma unroll
    for (int o = 16; o; o >>= 1) v += __shfl_xor_sync(0xFFFFFFFFu, v, o);
    return v;
}
__device__ __forceinline__ float dot4(float4 a, float4 b) {
    return a.x * b.x + a.y * b.y + a.z * b.z + a.w * b.w;
}

__device__ __forceinline__ void issue_load(const float* __restrict__ x,
                                           Smem* sm, int w, int b) {
    const uint32_t bytes = (w ? 33u : 32u) * 1024u;
    const float*   src   = x + (size_t)(w ? (w * WTOK - 1) : 0) * 256;
    const uint32_t dst   = smem_u32(sm->tile[b]) + (w ? 0u : 1024u);
    const uint32_t mb    = smem_u32(&sm->mbar[b]);
    asm volatile("mbarrier.arrive.expect_tx.shared::cta.b64 _, [%0], %1;"
                 :: "r"(mb), "r"(bytes) : "memory");
    asm volatile("cp.async.bulk.shared::cta.global.mbarrier::complete_tx::bytes [%0], [%1], %2, [%3];"
                 :: "r"(dst), "l"(src), "r"(bytes), "r"(mb) : "memory");
}

__global__ void __launch_bounds__(512, 2)
focus_kernel(const float* __restrict__ x,
             float* __restrict__ mask_out,        // N floats (0/1)
             float* __restrict__ comp_out,        // N*256 floats
             int nwin)
{
    extern __shared__ __align__(128) char smem_raw[];
    Smem* sm = reinterpret_cast<Smem*>(smem_raw);

    const int warp = threadIdx.x >> 5;
    const int lane = threadIdx.x & 31;
    const int rA   = 2 * warp + 1;       // tile row of token t0+2*warp
    const int rB   = 2 * warp + 2;

    if (threadIdx.x == 0) {
        #pragma unroll
        for (int i = 0; i < NBUF; i++)
            asm volatile("mbarrier.init.shared::cta.b64 [%0], %1;"
                         :: "r"(smem_u32(&sm->mbar[i])), "r"(1) : "memory");
        // prologue: 2-deep lookahead
        issue_load(x, sm, blockIdx.x, 0);
        if ((int)blockIdx.x + NCTA < nwin) issue_load(x, sm, blockIdx.x + NCTA, 1);
    }
    __syncthreads();

    int it = 0;
    for (int w = blockIdx.x; w < nwin; w += NCTA, ++it) {
        const int b  = it % NBUF;
        const int t0 = w * WTOK;

        // Wait for this buffer's load (parity = use-count & 1).
        {
            const uint32_t mb = smem_u32(&sm->mbar[b]);
            const unsigned ph = (unsigned)(it / NBUF) & 1u;
            asm volatile(
                "{\n\t.reg .pred P;\n\t"
                "W%=:\n\t"
                "mbarrier.try_wait.parity.acquire.cta.shared::cta.b64 P, [%0], %1;\n\t"
                "@P bra D%=;\n\t"
                "bra W%=;\n\t"
                "D%=:\n\t}"
                :: "r"(mb), "r"(ph) : "memory");
        }

        float4* t4 = (float4*)sm->tile[b];
        if (w == 0 && warp == 0) {       // deterministic row 0 for window 0
            const float4 z = make_float4(0.f, 0.f, 0.f, 0.f);
            t4[lane] = z;  t4[32 + lane] = z;
        }

        // ---- Phase 1: norms (warp 0 also does row 0) ----
        const float4 a0 = t4[rA * 64 + lane], a1 = t4[rA * 64 + 32 + lane];
        const float4 b0 = t4[rB * 64 + lane], b1 = t4[rB * 64 + 32 + lane];
        {
            float sa = dot4(a0, a0) + dot4(a1, a1);
            float sb = dot4(b0, b0) + dot4(b1, b1);
            #pragma unroll
            for (int o = 16; o; o >>= 1) {
                sa += __shfl_xor_sync(0xFFFFFFFFu, sa, o);
                sb += __shfl_xor_sync(0xFFFFFFFFu, sb, o);
            }
            if (lane == 0) {
                sm->inv_s[rA] = 1.0f / fmaxf(sqrtf(sa), 1e-12f);
                sm->inv_s[rB] = 1.0f / fmaxf(sqrtf(sb), 1e-12f);
            }
            if (warp == 0) {
                float4 p0 = t4[lane], p1 = t4[32 + lane];
                float sp = warp_sum(dot4(p0, p0) + dot4(p1, p1));
                if (lane == 0) sm->inv_s[0] = 1.0f / fmaxf(sqrtf(sp), 1e-12f);
            }
        }
        __syncthreads();

        const float invA = sm->inv_s[rA];
        const float invB = sm->inv_s[rB];

        // ---- Phase 2: adjacent dots (stage-3 masks) + weighted column sums ----
        bool m3A, m3B;
        {
            const float4 p0 = t4[(rA - 1) * 64 + lane];
            const float4 p1 = t4[(rA - 1) * 64 + 32 + lane];
            float dA = dot4(a0, p0) + dot4(a1, p1);
            float dB = dot4(b0, a0) + dot4(b1, a1);
            #pragma unroll
            for (int o = 16; o; o >>= 1) {
                dA += __shfl_xor_sync(0xFFFFFFFFu, dA, o);
                dB += __shfl_xor_sync(0xFFFFFFFFu, dB, o);
            }
            m3A = ((t0 + 2 * warp) == 0) || (invA * sm->inv_s[rA - 1] * dA < 0.7f);
            m3B = (invB * invA * dB < 0.7f);
        }
        if (threadIdx.x < 256) {
            const float* tb = sm->tile[b];
            const int c = threadIdx.x;
            float acc = 0.0f;
            #pragma unroll
            for (int r = 1; r <= WTOK; r++) acc += tb[r * 256 + c] * sm->inv_s[r];
            sm->s_s[c] = acc;
        }
        __syncthreads();

        // ---- Phase 3: zero masked rows in place + mean-similarity dots ----
        {
            const float4 z = make_float4(0.f, 0.f, 0.f, 0.f);
            if (!m3A) { t4[rA * 64 + lane] = z;  t4[rA * 64 + 32 + lane] = z; }
            if (!m3B) { t4[rB * 64 + lane] = z;  t4[rB * 64 + 32 + lane] = z; }

            const float4* sv = (const float4*)sm->s_s;
            const float4 s0 = sv[lane], s1 = sv[32 + lane];
            float dA = dot4(a0, s0) + dot4(a1, s1);
            float dB = dot4(b0, s0) + dot4(b1, s1);
            #pragma unroll
            for (int o = 16; o; o >>= 1) {
                dA += __shfl_xor_sync(0xFFFFFFFFu, dA, o);
                dB += __shfl_xor_sync(0xFFFFFFFFu, dB, o);
            }
            if (lane == 0) {
                sm->ms_s[2 * warp]     = invA * dA * (1.0f / 32.0f);
                sm->ms_s[2 * warp + 1] = invB * dB * (1.0f / 32.0f);
            }
        }
        __syncthreads();

        // ---- Phase 4: bulk store + 2-ahead prefetch (thread 0) || stats (warp 0) ----
        if (threadIdx.x == 0) {
            asm volatile("fence.proxy.async.shared::cta;" ::: "memory");
            asm volatile("cp.async.bulk.global.shared::cta.bulk_group [%0], [%1], %2;"
                         :: "l"(comp_out + (size_t)t0 * 256),
                            "r"(smem_u32(sm->tile[b]) + 1024u),
                            "r"(32u * 1024u) : "memory");
            asm volatile("cp.async.bulk.commit_group;" ::: "memory");
            const int wn = w + 2 * NCTA;
            if (wn < nwin) {
                // buffer (it+2)%NBUF was last used by store(it-1); require that
                // store's smem reads done (allow the just-issued store pending).
                asm volatile("cp.async.bulk.wait_group.read 1;" ::: "memory");
                issue_load(x, sm, wn, (it + 2) % NBUF);
            }
        }
        if (warp == 0) {
            const float m = sm->ms_s[lane];
            float mu = warp_sum(m) * (1.0f / 32.0f);
            float d = m - mu;
            float var = warp_sum(d * d) * (1.0f / 31.0f);   // ddof=1
            float sd = sqrtf(var);
            bool keep = !(m > mu + sd);
            unsigned bal = __ballot_sync(0xFFFFFFFFu, keep);
            if (bal == 0u) {
                // fallback: keep argmin(mean_sim), first index on ties
                float bv = m; int bi = lane;
                #pragma unroll
                for (int o = 16; o; o >>= 1) {
                    float ov = __shfl_xor_sync(0xFFFFFFFFu, bv, o);
                    int   oi = __shfl_xor_sync(0xFFFFFFFFu, bi, o);
                    if (ov < bv || (ov == bv && oi < bi)) { bv = ov; bi = oi; }
                }
                keep = (lane == bi);
            }
            mask_out[t0 + lane] = keep ? 1.0f : 0.0f;
        }
    }

    // drain outstanding bulk stores before CTA exit
    if (threadIdx.x == 0) {
        asm volatile("cp.async.bulk.wait_group 0;" ::: "memory");
    }
}

extern "C" void kernel_launch(void* const* d_in, const int* in_sizes, int n_in,
                              void* d_out, int out_size)
{
    const float* x = (const float*)d_in[0];
    const int N = in_sizes[0] / 256;       // tokens
    const int nwin = N / WTOK;             // windows

    float* out = (float*)d_out;
    float* mask_out = out;                 // first N floats
    float* comp_out = out + N;             // N*256 floats

    cudaFuncSetAttribute(focus_kernel,
                         cudaFuncAttributeMaxDynamicSharedMemorySize,
                         (int)sizeof(Smem));
    focus_kernel<<<NCTA, 512, sizeof(Smem)>>>(x, mask_out, comp_out, nwin);
}

// round 8
// speedup vs baseline: 1.2124x; 1.2124x over previous
#include <cuda_runtime.h>
#include <cstdint>

// FocusModules, one-shot TMA per window, 256-thread CTAs, 6 CTAs/SM.
// x: [N, 256] f32.  out (float32): [ mask1 (N) | compressed (N*256) ].
//
// One CTA per 32-token window (8192 CTAs). Tile rows 0..32 = tokens t0-1..t0+31.
// mean_sim[i] = inv_i * dot(raw_i, s)/32, s[c] = sum_r raw[r][c]*inv_r.
// 6 CTAs/SM -> 6 concurrent bulk load/store streams per SM at 48 warps/SM.

#define WTOK 32

struct __align__(128) Smem {
    float tile[33 * 256];        // 33 KB
    float s_s[256];              // weighted column sums
    float inv_s[33];             // per-row 1/||x||
    float ms_s[WTOK];            // per-token mean similarity
    unsigned long long mbar;
};

__device__ __forceinline__ uint32_t smem_u32(const void* p) {
    return (uint32_t)__cvta_generic_to_shared(p);
}
__device__ __forceinline__ float warp_sum(float v) {
    #pragma unroll
    for (int o = 16; o; o >>= 1) v += __shfl_xor_sync(0xFFFFFFFFu, v, o);
    return v;
}
__device__ __forceinline__ float dot4(float4 a, float4 b) {
    return a.x * b.x + a.y * b.y + a.z * b.z + a.w * b.w;
}

__global__ void __launch_bounds__(256, 6)
focus_kernel(const float* __restrict__ x,
             float* __restrict__ mask_out,        // N floats (0/1)
             float* __restrict__ comp_out)        // N*256 floats
{
    extern __shared__ __align__(128) char smem_raw[];
    Smem* sm = reinterpret_cast<Smem*>(smem_raw);

    const int w    = blockIdx.x;
    const int warp = threadIdx.x >> 5;   // 0..7, owns tokens 4w..4w+3
    const int lane = threadIdx.x & 31;
    const int t0   = w * WTOK;
    const int r0   = 4 * warp + 1;       // first tile row owned by this warp

    // ---- Bulk load rows t0-1 .. t0+31 (w=0: rows t0..t0+31 into tile+1KB) ----
    const uint32_t mb = smem_u32(&sm->mbar);
    if (threadIdx.x == 0) {
        asm volatile("mbarrier.init.shared::cta.b64 [%0], %1;" :: "r"(mb), "r"(1) : "memory");
        // make the init visible before the async proxy uses the barrier
        asm volatile("fence.proxy.async.shared::cta;" ::: "memory");
        const uint32_t bytes = (w ? 33u : 32u) * 1024u;
        const float*   src   = x + (size_t)(w ? (t0 - 1) : 0) * 256;
        const uint32_t dst   = smem_u32(sm->tile) + (w ? 0u : 1024u);
        asm volatile("mbarrier.arrive.expect_tx.shared::cta.b64 _, [%0], %1;"
                     :: "r"(mb), "r"(bytes) : "memory");
        asm volatile("cp.async.bulk.shared::cta.global.mbarrier::complete_tx::bytes [%0], [%1], %2, [%3];"
                     :: "r"(dst), "l"(src), "r"(bytes), "r"(mb) : "memory");
    }
    __syncthreads();
    asm volatile(
        "{\n\t.reg .pred P;\n\t"
        "W%=:\n\t"
        "mbarrier.try_wait.parity.acquire.cta.shared::cta.b64 P, [%0], 0;\n\t"
        "@P bra D%=;\n\t"
        "bra W%=;\n\t"
        "D%=:\n\t}"
        :: "r"(mb) : "memory");

    float4* t4 = (float4*)sm->tile;
    if (w == 0 && warp == 0) {           // deterministic row 0 for window 0
        const float4 z = make_float4(0.f, 0.f, 0.f, 0.f);
        t4[lane] = z;  t4[32 + lane] = z;
    }

    // ---- Phase 1: norms of the 4 owned rows (warp 0 also row 0) ----
    {
        float p[4];
        #pragma unroll
        for (int i = 0; i < 4; i++) {
            const float4 lo = t4[(r0 + i) * 64 + lane];
            const float4 hi = t4[(r0 + i) * 64 + 32 + lane];
            p[i] = dot4(lo, lo) + dot4(hi, hi);
        }
        #pragma unroll
        for (int o = 16; o; o >>= 1) {
            p[0] += __shfl_xor_sync(0xFFFFFFFFu, p[0], o);
            p[1] += __shfl_xor_sync(0xFFFFFFFFu, p[1], o);
            p[2] += __shfl_xor_sync(0xFFFFFFFFu, p[2], o);
            p[3] += __shfl_xor_sync(0xFFFFFFFFu, p[3], o);
        }
        if (lane == 0) {
            #pragma unroll
            for (int i = 0; i < 4; i++)
                sm->inv_s[r0 + i] = 1.0f / fmaxf(sqrtf(p[i]), 1e-12f);
        }
        if (warp == 0) {
            const float4 q0 = t4[lane], q1 = t4[32 + lane];
            float sp = warp_sum(dot4(q0, q0) + dot4(q1, q1));
            if (lane == 0) sm->inv_s[0] = 1.0f / fmaxf(sqrtf(sp), 1e-12f);
        }
    }
    __syncthreads();

    // ---- Phase 2: column sums + adjacent-dot partials (all read-only) ----
    float dadj[4];
    {
        const int c = threadIdx.x;        // 256 threads, one column each
        float acc = 0.0f;
        #pragma unroll
        for (int r = 1; r <= WTOK; r++) acc += sm->tile[r * 256 + c] * sm->inv_s[r];
        sm->s_s[c] = acc;

        float4 p0 = t4[(r0 - 1) * 64 + lane];
        float4 p1 = t4[(r0 - 1) * 64 + 32 + lane];
        #pragma unroll
        for (int i = 0; i < 4; i++) {
            const float4 lo = t4[(r0 + i) * 64 + lane];
            const float4 hi = t4[(r0 + i) * 64 + 32 + lane];
            dadj[i] = dot4(lo, p0) + dot4(hi, p1);
            p0 = lo;  p1 = hi;
        }
        #pragma unroll
        for (int o = 16; o; o >>= 1) {
            dadj[0] += __shfl_xor_sync(0xFFFFFFFFu, dadj[0], o);
            dadj[1] += __shfl_xor_sync(0xFFFFFFFFu, dadj[1], o);
            dadj[2] += __shfl_xor_sync(0xFFFFFFFFu, dadj[2], o);
            dadj[3] += __shfl_xor_sync(0xFFFFFFFFu, dadj[3], o);
        }
    }
    __syncthreads();   // s_s ready; all raw-row readers done before zeroing

    // ---- Phase 3: mean-sim dots + zero masked rows in place ----
    {
        const float4* sv = (const float4*)sm->s_s;
        const float4 s0 = sv[lane], s1 = sv[32 + lane];
        const float4 z  = make_float4(0.f, 0.f, 0.f, 0.f);
        float dms[4];
        #pragma unroll
        for (int i = 0; i < 4; i++) {
            const int r = r0 + i;
            const float4 lo = t4[r * 64 + lane];
            const float4 hi = t4[r * 64 + 32 + lane];
            dms[i] = dot4(lo, s0) + dot4(hi, s1);
            const bool m3 = ((t0 + 4 * warp + i) == 0) ||
                            (sm->inv_s[r] * sm->inv_s[r - 1] * dadj[i] < 0.7f);
            if (!m3) { t4[r * 64 + lane] = z;  t4[r * 64 + 32 + lane] = z; }
        }
        #pragma unroll
        for (int o = 16; o; o >>= 1) {
            dms[0] += __shfl_xor_sync(0xFFFFFFFFu, dms[0], o);
            dms[1] += __shfl_xor_sync(0xFFFFFFFFu, dms[1], o);
            dms[2] += __shfl_xor_sync(0xFFFFFFFFu, dms[2], o);
            dms[3] += __shfl_xor_sync(0xFFFFFFFFu, dms[3], o);
        }
        if (lane == 0) {
            #pragma unroll
            for (int i = 0; i < 4; i++)
                sm->ms_s[4 * warp + i] = sm->inv_s[r0 + i] * dms[i] * (1.0f / 32.0f);
        }
    }
    __syncthreads();

    // ---- Phase 4: bulk store (thread 0) || window stats (warp 0) ----
    if (threadIdx.x == 0) {
        asm volatile("fence.proxy.async.shared::cta;" ::: "memory");
        asm volatile("cp.async.bulk.global.shared::cta.bulk_group [%0], [%1], %2;"
                     :: "l"(comp_out + (size_t)t0 * 256),
                        "r"(smem_u32(sm->tile) + 1024u),
                        "r"(32u * 1024u) : "memory");
        asm volatile("cp.async.bulk.commit_group;" ::: "memory");
    }
    if (warp == 0) {
        const float m = sm->ms_s[lane];
        float mu = warp_sum(m) * (1.0f / 32.0f);
        float d = m - mu;
        float var = warp_sum(d * d) * (1.0f / 31.0f);   // ddof=1
        float sd = sqrtf(var);
        bool keep = !(m > mu + sd);
        unsigned bal = __ballot_sync(0xFFFFFFFFu, keep);
        if (bal == 0u) {
            // fallback: keep argmin(mean_sim), first index on ties
            float bv = m; int bi = lane;
            #pragma unroll
            for (int o = 16; o; o >>= 1) {
                float ov = __shfl_xor_sync(0xFFFFFFFFu, bv, o);
                int   oi = __shfl_xor_sync(0xFFFFFFFFu, bi, o);
                if (ov < bv || (ov == bv && oi < bi)) { bv = ov; bi = oi; }
            }
            keep = (lane == bi);
        }
        mask_out[t0 + lane] = keep ? 1.0f : 0.0f;
    }
    // drain the bulk store before the CTA retires (smem + writes must complete)
    if (threadIdx.x == 0) {
        asm volatile("cp.async.bulk.wait_group 0;" ::: "memory");
    }
}

extern "C" void kernel_launch(void* const* d_in, const int* in_sizes, int n_in,
                              void* d_out, int out_size)
{
    const float* x = (const float*)d_in[0];
    const int N = in_sizes[0] / 256;       // tokens
    const int nwin = N / WTOK;             // windows

    float* out = (float*)d_out;
    float* mask_out = out;                 // first N floats
    float* comp_out = out + N;             // N*256 floats

    cudaFuncSetAttribute(focus_kernel,
                         cudaFuncAttributeMaxDynamicSharedMemorySize,
                         (int)sizeof(Smem));
    focus_kernel<<<nwin, 256, sizeof(Smem)>>>(x, mask_out, comp_out);
}